// round 2
// baseline (speedup 1.0000x reference)
#include <cuda_runtime.h>
#include <math.h>

// ---------------------------------------------------------------------------
// Problem constants
// ---------------------------------------------------------------------------
#define NPTS      98304      // 2 * 1024 * 48
#define NPB       49152      // points per batch (1024*48)
#define DH        512        // hidden / latent dim
#define NBLK      5
#define NFREQ     10
#define IMGH      128
#define IMGW      128
#define DENC      64         // 63 padded to 64

// ---------------------------------------------------------------------------
// Scratch (static device globals; no runtime allocation allowed)
// ---------------------------------------------------------------------------
__device__ float g_enc[NPTS * DENC];        // padded encoding
__device__ float g_uv[NPTS * 2];            // projected uv
__device__ float g_aligned[NPTS * DH];      // bilinear-sampled features
__device__ float g_h[NPTS * DH];            // residual stream
__device__ float g_net[NPTS * DH];          // intermediate
__device__ float g_win[DENC * DH];          // lin_in_w padded 63->64 rows

// ---------------------------------------------------------------------------
// Pad lin_in_w (63x512) into g_win (64x512), zero last row
// ---------------------------------------------------------------------------
__global__ void pad_win_kernel(const float* __restrict__ w) {
    int t = blockIdx.x * blockDim.x + threadIdx.x;
    if (t >= DENC * DH) return;
    int k = t / DH;
    g_win[t] = (k < 63) ? w[t] : 0.0f;
}

// ---------------------------------------------------------------------------
// Per-point: camera transform, projection (uv), positional encoding
// ---------------------------------------------------------------------------
__global__ void enc_kernel(const float* __restrict__ xyz,
                           const float* __restrict__ c2w,
                           const float* __restrict__ kmat) {
    int n = blockIdx.x * blockDim.x + threadIdx.x;
    if (n >= NPTS) return;
    int b = n / NPB;

    float p0 = xyz[n * 3 + 0];
    float p1 = xyz[n * 3 + 1];
    float p2 = xyz[n * 3 + 2];

    const float* M = c2w + b * 16;
    float q0 = p0 - M[0 * 4 + 3];
    float q1 = p1 - M[1 * 4 + 3];
    float q2 = p2 - M[2 * 4 + 3];

    // cam[i] = sum_j rot[j][i] * q[j]   (R^T)
    float cam[3];
    #pragma unroll
    for (int i = 0; i < 3; i++)
        cam[i] = M[0 * 4 + i] * q0 + M[1 * 4 + i] * q1 + M[2 * 4 + i] * q2;

    const float* K = kmat + b * 9;
    float uw = K[0] * cam[0] + K[1] * cam[1] + K[2] * cam[2];
    float vw = K[3] * cam[0] + K[4] * cam[1] + K[5] * cam[2];
    float zw = K[6] * cam[0] + K[7] * cam[1] + K[8] * cam[2];
    float z = (fabsf(zw) < 1e-6f) ? 1e-6f : zw;
    g_uv[n * 2 + 0] = uw / z;
    g_uv[n * 2 + 1] = vw / z;

    float* E = g_enc + (size_t)n * DENC;
    E[0] = cam[0]; E[1] = cam[1]; E[2] = cam[2];
    const float TWO_PI = 6.283185307179586f;
    #pragma unroll
    for (int axis = 0; axis < 3; axis++) {
        #pragma unroll
        for (int f = 0; f < NFREQ; f++) {
            float s = TWO_PI * cam[axis] * (float)(1 << f);
            E[3  + axis * NFREQ + f] = sinf(s);
            E[33 + axis * NFREQ + f] = cosf(s);
        }
    }
    E[63] = 0.0f;
}

// ---------------------------------------------------------------------------
// Bilinear feature gather: one block per point, 256 threads over 512 channels
// ---------------------------------------------------------------------------
__global__ void bilinear_kernel(const float* __restrict__ feat) {
    int n = blockIdx.x;
    int b = n / NPB;

    float u = g_uv[n * 2 + 0];
    float v = g_uv[n * 2 + 1];
    float x = fminf(fmaxf(u, 0.0f), (float)(IMGW - 1));
    float y = fminf(fmaxf(v, 0.0f), (float)(IMGH - 1));
    float x0 = floorf(x), y0 = floorf(y);
    int x0i = (int)x0, y0i = (int)y0;
    int x1i = min(x0i + 1, IMGW - 1);
    int y1i = min(y0i + 1, IMGH - 1);
    float wx = x - x0, wy = y - y0;
    float w00 = (1.0f - wx) * (1.0f - wy);
    float w01 = wx * (1.0f - wy);
    float w10 = (1.0f - wx) * wy;
    float w11 = wx * wy;

    const float* fb = feat + (size_t)b * DH * IMGH * IMGW;
    int o00 = y0i * IMGW + x0i;
    int o01 = y0i * IMGW + x1i;
    int o10 = y1i * IMGW + x0i;
    int o11 = y1i * IMGW + x1i;

    float* out = g_aligned + (size_t)n * DH;
    for (int c = threadIdx.x; c < DH; c += blockDim.x) {
        const float* base = fb + (size_t)c * (IMGH * IMGW);
        float f00 = base[o00];
        float f01 = base[o01];
        float f10 = base[o10];
        float f11 = base[o11];
        out[c] = f00 * w00 + f01 * w01 + f10 * w10 + f11 * w11;
    }
}

// ---------------------------------------------------------------------------
// Tiled SGEMM: C[M,N] = op(A)[M,K] @ B[K,N] (+ bias) (+ existing C)
//   RELU_A:   apply relu to A elements on load
//   ACCUM:    C = C + result (residual) instead of overwrite
// Tile 128x128x16, 256 threads, 8x8 per thread. M%128==0, N%128==0, K%16==0.
// ---------------------------------------------------------------------------
template <bool RELU_A, bool ACCUM>
__global__ void __launch_bounds__(256, 2)
gemm_kernel(const float* __restrict__ A,
            const float* __restrict__ B,
            const float* __restrict__ bias,
            float* __restrict__ C,
            int M, int N, int K) {
    const int BM = 128, BN = 128, BK = 16;
    __shared__ float As[BK][BM + 4];
    __shared__ float Bs[BK][BN];

    int tid = threadIdx.x;
    int tx = tid & 15;       // 0..15  -> col group
    int ty = tid >> 4;       // 0..15  -> row group

    int rowBase = blockIdx.y * BM;
    int colBase = blockIdx.x * BN;

    // global-load mappings
    int a_row = tid >> 2;            // 0..63 (two passes)
    int a_kc  = (tid & 3) * 4;       // 0,4,8,12
    int b_kr  = tid >> 5;            // 0..7 (two passes)
    int b_nc  = (tid & 31) * 4;      // 0..124

    float acc[8][8];
    #pragma unroll
    for (int i = 0; i < 8; i++)
        #pragma unroll
        for (int j = 0; j < 8; j++) acc[i][j] = 0.0f;

    for (int k0 = 0; k0 < K; k0 += BK) {
        // load A tile (transposed into smem)
        #pragma unroll
        for (int pass = 0; pass < 2; pass++) {
            int m = a_row + pass * 64;
            const float4 v = *(const float4*)(A + (size_t)(rowBase + m) * K + k0 + a_kc);
            float vx = v.x, vy = v.y, vz = v.z, vw = v.w;
            if (RELU_A) {
                vx = fmaxf(vx, 0.0f); vy = fmaxf(vy, 0.0f);
                vz = fmaxf(vz, 0.0f); vw = fmaxf(vw, 0.0f);
            }
            As[a_kc + 0][m] = vx;
            As[a_kc + 1][m] = vy;
            As[a_kc + 2][m] = vz;
            As[a_kc + 3][m] = vw;
        }
        // load B tile
        #pragma unroll
        for (int pass = 0; pass < 2; pass++) {
            int kr = b_kr + pass * 8;
            const float4 v = *(const float4*)(B + (size_t)(k0 + kr) * N + colBase + b_nc);
            *(float4*)&Bs[kr][b_nc] = v;
        }
        __syncthreads();

        #pragma unroll
        for (int kk = 0; kk < BK; kk++) {
            float a[8], bb[8];
            float4 a0 = *(const float4*)&As[kk][ty * 8];
            float4 a1 = *(const float4*)&As[kk][ty * 8 + 4];
            float4 b0 = *(const float4*)&Bs[kk][tx * 8];
            float4 b1 = *(const float4*)&Bs[kk][tx * 8 + 4];
            a[0]=a0.x; a[1]=a0.y; a[2]=a0.z; a[3]=a0.w;
            a[4]=a1.x; a[5]=a1.y; a[6]=a1.z; a[7]=a1.w;
            bb[0]=b0.x; bb[1]=b0.y; bb[2]=b0.z; bb[3]=b0.w;
            bb[4]=b1.x; bb[5]=b1.y; bb[6]=b1.z; bb[7]=b1.w;
            #pragma unroll
            for (int i = 0; i < 8; i++)
                #pragma unroll
                for (int j = 0; j < 8; j++)
                    acc[i][j] = fmaf(a[i], bb[j], acc[i][j]);
        }
        __syncthreads();
    }

    // epilogue
    int m0 = rowBase + ty * 8;
    int n0 = colBase + tx * 8;
    float bvals[8];
    #pragma unroll
    for (int j = 0; j < 8; j++) bvals[j] = bias[n0 + j];

    #pragma unroll
    for (int i = 0; i < 8; i++) {
        float* crow = C + (size_t)(m0 + i) * N + n0;
        #pragma unroll
        for (int j = 0; j < 8; j++) {
            float v = acc[i][j] + bvals[j];
            if (ACCUM) v += crow[j];
            crow[j] = v;
        }
    }
}

// ---------------------------------------------------------------------------
// Final: sigma = exp(relu(h) @ w_out + b_out). One warp per point.
// ---------------------------------------------------------------------------
__global__ void sigma_kernel(const float* __restrict__ w_out,
                             const float* __restrict__ b_out,
                             float* __restrict__ out) {
    int gtid = blockIdx.x * blockDim.x + threadIdx.x;
    int n = gtid >> 5;
    int lane = gtid & 31;
    if (n >= NPTS) return;

    const float* hrow = g_h + (size_t)n * DH;
    float s = 0.0f;
    #pragma unroll
    for (int k = lane; k < DH; k += 32)
        s = fmaf(fmaxf(hrow[k], 0.0f), w_out[k], s);

    #pragma unroll
    for (int off = 16; off > 0; off >>= 1)
        s += __shfl_down_sync(0xFFFFFFFF, s, off);

    if (lane == 0) out[n] = expf(s + b_out[0]);
}

// ---------------------------------------------------------------------------
// Launch
// ---------------------------------------------------------------------------
static float* sym(const void* s) {
    void* p = nullptr;
    cudaGetSymbolAddress(&p, s);
    return (float*)p;
}

extern "C" void kernel_launch(void* const* d_in, const int* in_sizes, int n_in,
                              void* d_out, int out_size) {
    const float* world_xyz = (const float*)d_in[0];
    const float* c2w       = (const float*)d_in[1];
    const float* k_mat     = (const float*)d_in[2];
    const float* features  = (const float*)d_in[3];
    const float* lin_in_w  = (const float*)d_in[4];
    const float* lin_in_b  = (const float*)d_in[5];
    const float* lin_z_w   = (const float*)d_in[6];
    const float* lin_z_b   = (const float*)d_in[7];
    const float* fc0_w     = (const float*)d_in[8];
    const float* fc0_b     = (const float*)d_in[9];
    const float* fc1_w     = (const float*)d_in[10];
    const float* fc1_b     = (const float*)d_in[11];
    const float* lin_out_w = (const float*)d_in[12];
    const float* lin_out_b = (const float*)d_in[13];
    float* out = (float*)d_out;

    float* p_enc     = sym(g_enc);
    float* p_aligned = sym(g_aligned);
    float* p_h       = sym(g_h);
    float* p_net     = sym(g_net);
    float* p_win     = sym(g_win);

    pad_win_kernel<<<(DENC * DH + 255) / 256, 256>>>(lin_in_w);
    enc_kernel<<<(NPTS + 255) / 256, 256>>>(world_xyz, c2w, k_mat);
    bilinear_kernel<<<NPTS, 256>>>(features);

    dim3 grid(DH / 128, NPTS / 128);  // (4, 768)

    // h = enc @ win + b
    gemm_kernel<false, false><<<grid, 256>>>(p_enc, p_win, lin_in_b, p_h,
                                             NPTS, DH, DENC);

    for (int i = 0; i < NBLK; i++) {
        const float* wz  = lin_z_w + (size_t)i * DH * DH;
        const float* bz  = lin_z_b + (size_t)i * DH;
        const float* w0  = fc0_w   + (size_t)i * DH * DH;
        const float* b0  = fc0_b   + (size_t)i * DH;
        const float* w1  = fc1_w   + (size_t)i * DH * DH;
        const float* b1  = fc1_b   + (size_t)i * DH;

        // h += aligned @ wz + bz
        gemm_kernel<false, true><<<grid, 256>>>(p_aligned, wz, bz, p_h,
                                                NPTS, DH, DH);
        // net = relu(h) @ w0 + b0
        gemm_kernel<true, false><<<grid, 256>>>(p_h, w0, b0, p_net,
                                                NPTS, DH, DH);
        // h += relu(net) @ w1 + b1
        gemm_kernel<true, true><<<grid, 256>>>(p_net, w1, b1, p_h,
                                               NPTS, DH, DH);
    }

    sigma_kernel<<<(NPTS * 32 + 255) / 256, 256>>>(lin_out_w, lin_out_b, out);
}

// round 4
// speedup vs baseline: 2.0098x; 2.0098x over previous
#include <cuda_runtime.h>
#include <cuda_bf16.h>
#include <cstdint>
#include <math.h>

// ---------------------------------------------------------------------------
// Problem constants
// ---------------------------------------------------------------------------
#define NPTS      98304
#define NPB       49152
#define DH        512
#define NBLK      5
#define NFREQ     10
#define IMGH      128
#define IMGW      128
#define DENC      64

typedef __nv_bfloat16 bf16;
typedef __nv_bfloat162 bf162;

// ---------------------------------------------------------------------------
// Scratch
// ---------------------------------------------------------------------------
__device__ float g_enc[NPTS * DENC];
__device__ float g_uv[NPTS * 2];
__device__ float g_h[NPTS * DH];            // fp32 residual stream
__device__ float g_win[DENC * DH];
// bf16 hi/lo activation splits
__device__ bf16 g_alh[NPTS * DH];
__device__ bf16 g_all[NPTS * DH];
__device__ bf16 g_th[NPTS * DH];
__device__ bf16 g_tl[NPTS * DH];
__device__ bf16 g_uh[NPTS * DH];
__device__ bf16 g_ul[NPTS * DH];
// transposed weight splits [n][k]
__device__ bf16 g_wzh[NBLK * DH * DH];
__device__ bf16 g_wzl[NBLK * DH * DH];
__device__ bf16 g_w0h[NBLK * DH * DH];
__device__ bf16 g_w0l[NBLK * DH * DH];
__device__ bf16 g_w1h[NBLK * DH * DH];
__device__ bf16 g_w1l[NBLK * DH * DH];

// ---------------------------------------------------------------------------
// PTX helpers (baseline ISA only: mma.sync / ldmatrix / cp.async)
// ---------------------------------------------------------------------------
__device__ __forceinline__ uint32_t smem_u32(const void* p) {
    uint32_t a;
    asm("{ .reg .u64 t; cvta.to.shared.u64 t, %1; cvt.u32.u64 %0, t; }" : "=r"(a) : "l"(p));
    return a;
}
__device__ __forceinline__ void ldsm_x4(uint32_t& r0, uint32_t& r1, uint32_t& r2,
                                        uint32_t& r3, uint32_t addr) {
    asm volatile("ldmatrix.sync.aligned.m8n8.x4.shared.b16 {%0,%1,%2,%3}, [%4];"
                 : "=r"(r0), "=r"(r1), "=r"(r2), "=r"(r3) : "r"(addr));
}
__device__ __forceinline__ void mma_bf16(float* d, const uint32_t* a, const uint32_t* b) {
    asm volatile(
        "mma.sync.aligned.m16n8k16.row.col.f32.bf16.bf16.f32 "
        "{%0,%1,%2,%3}, {%4,%5,%6,%7}, {%8,%9}, {%0,%1,%2,%3};"
        : "+f"(d[0]), "+f"(d[1]), "+f"(d[2]), "+f"(d[3])
        : "r"(a[0]), "r"(a[1]), "r"(a[2]), "r"(a[3]), "r"(b[0]), "r"(b[1]));
}
__device__ __forceinline__ void cp16(uint32_t dst, const void* src) {
    asm volatile("cp.async.cg.shared.global [%0], [%1], 16;" :: "r"(dst), "l"(src));
}
#define CP_COMMIT() asm volatile("cp.async.commit_group;" ::: "memory")
#define CP_WAIT(n)  asm volatile("cp.async.wait_group %0;" :: "n"(n) : "memory")

// ---------------------------------------------------------------------------
// Small prep kernels
// ---------------------------------------------------------------------------
__global__ void pad_win_kernel(const float* __restrict__ w) {
    int t = blockIdx.x * blockDim.x + threadIdx.x;
    if (t >= DENC * DH) return;
    int k = t / DH;
    g_win[t] = (k < 63) ? w[t] : 0.0f;
}

__global__ void enc_kernel(const float* __restrict__ xyz,
                           const float* __restrict__ c2w,
                           const float* __restrict__ kmat) {
    int n = blockIdx.x * blockDim.x + threadIdx.x;
    if (n >= NPTS) return;
    int b = n / NPB;
    float p0 = xyz[n * 3 + 0], p1 = xyz[n * 3 + 1], p2 = xyz[n * 3 + 2];
    const float* M = c2w + b * 16;
    float q0 = p0 - M[3], q1 = p1 - M[7], q2 = p2 - M[11];
    float cam[3];
    #pragma unroll
    for (int i = 0; i < 3; i++)
        cam[i] = M[0 * 4 + i] * q0 + M[1 * 4 + i] * q1 + M[2 * 4 + i] * q2;
    const float* K = kmat + b * 9;
    float uw = K[0] * cam[0] + K[1] * cam[1] + K[2] * cam[2];
    float vw = K[3] * cam[0] + K[4] * cam[1] + K[5] * cam[2];
    float zw = K[6] * cam[0] + K[7] * cam[1] + K[8] * cam[2];
    float z = (fabsf(zw) < 1e-6f) ? 1e-6f : zw;
    g_uv[n * 2 + 0] = uw / z;
    g_uv[n * 2 + 1] = vw / z;
    float* E = g_enc + (size_t)n * DENC;
    E[0] = cam[0]; E[1] = cam[1]; E[2] = cam[2];
    const float TWO_PI = 6.283185307179586f;
    #pragma unroll
    for (int axis = 0; axis < 3; axis++)
        #pragma unroll
        for (int f = 0; f < NFREQ; f++) {
            float s = TWO_PI * cam[axis] * (float)(1 << f);
            E[3  + axis * NFREQ + f] = sinf(s);
            E[33 + axis * NFREQ + f] = cosf(s);
        }
    E[63] = 0.0f;
}

// bilinear gather -> write bf16 hi/lo split directly
__global__ void bilinear_kernel(const float* __restrict__ feat) {
    int n = blockIdx.x;
    int b = n / NPB;
    float u = g_uv[n * 2 + 0], v = g_uv[n * 2 + 1];
    float x = fminf(fmaxf(u, 0.0f), (float)(IMGW - 1));
    float y = fminf(fmaxf(v, 0.0f), (float)(IMGH - 1));
    float x0 = floorf(x), y0 = floorf(y);
    int x0i = (int)x0, y0i = (int)y0;
    int x1i = min(x0i + 1, IMGW - 1);
    int y1i = min(y0i + 1, IMGH - 1);
    float wx = x - x0, wy = y - y0;
    float w00 = (1.0f - wx) * (1.0f - wy);
    float w01 = wx * (1.0f - wy);
    float w10 = (1.0f - wx) * wy;
    float w11 = wx * wy;
    const float* fb = feat + (size_t)b * DH * IMGH * IMGW;
    int o00 = y0i * IMGW + x0i, o01 = y0i * IMGW + x1i;
    int o10 = y1i * IMGW + x0i, o11 = y1i * IMGW + x1i;
    size_t base = (size_t)n * DH;
    for (int c = threadIdx.x; c < DH; c += blockDim.x) {
        const float* fp = fb + (size_t)c * (IMGH * IMGW);
        float r = fp[o00] * w00 + fp[o01] * w01 + fp[o10] * w10 + fp[o11] * w11;
        bf16 hi = __float2bfloat16(r);
        bf16 lo = __float2bfloat16(r - __bfloat162float(hi));
        g_alh[base + c] = hi;
        g_all[base + c] = lo;
    }
}

// weights: W[l][k][n] fp32 -> hi/lo [l][n][k] bf16 (transposed)
__global__ void conv_w_kernel(const float* __restrict__ W, bf16* __restrict__ Oh,
                              bf16* __restrict__ Ol, int total) {
    int idx = blockIdx.x * blockDim.x + threadIdx.x;
    if (idx >= total) return;
    int l = idx >> 18;
    int rem = idx & 262143;
    int k = rem >> 9;
    int n = rem & 511;
    float x = W[idx];
    bf16 hi = __float2bfloat16(x);
    bf16 lo = __float2bfloat16(x - __bfloat162float(hi));
    int o = (l << 18) + n * DH + k;
    Oh[o] = hi;
    Ol[o] = lo;
}

// ---------------------------------------------------------------------------
// FFMA GEMM for the K=64 input layer (h = enc @ win + b)
// ---------------------------------------------------------------------------
__global__ void __launch_bounds__(256, 2)
gemm_in_kernel(const float* __restrict__ A, const float* __restrict__ B,
               const float* __restrict__ bias, float* __restrict__ C,
               int M, int N, int K) {
    const int BM = 128, BN = 128, BK = 16;
    __shared__ float As[BK][BM + 4];
    __shared__ float Bs[BK][BN];
    int tid = threadIdx.x;
    int tx = tid & 15, ty = tid >> 4;
    int rowBase = blockIdx.y * BM, colBase = blockIdx.x * BN;
    int a_row = tid >> 2, a_kc = (tid & 3) * 4;
    int b_kr = tid >> 5, b_nc = (tid & 31) * 4;
    float acc[8][8];
    #pragma unroll
    for (int i = 0; i < 8; i++)
        #pragma unroll
        for (int j = 0; j < 8; j++) acc[i][j] = 0.0f;
    for (int k0 = 0; k0 < K; k0 += BK) {
        #pragma unroll
        for (int pass = 0; pass < 2; pass++) {
            int m = a_row + pass * 64;
            const float4 v = *(const float4*)(A + (size_t)(rowBase + m) * K + k0 + a_kc);
            As[a_kc + 0][m] = v.x; As[a_kc + 1][m] = v.y;
            As[a_kc + 2][m] = v.z; As[a_kc + 3][m] = v.w;
        }
        #pragma unroll
        for (int pass = 0; pass < 2; pass++) {
            int kr = b_kr + pass * 8;
            *(float4*)&Bs[kr][b_nc] = *(const float4*)(B + (size_t)(k0 + kr) * N + colBase + b_nc);
        }
        __syncthreads();
        #pragma unroll
        for (int kk = 0; kk < BK; kk++) {
            float a[8], bb[8];
            float4 a0 = *(const float4*)&As[kk][ty * 8];
            float4 a1 = *(const float4*)&As[kk][ty * 8 + 4];
            float4 b0 = *(const float4*)&Bs[kk][tx * 8];
            float4 b1 = *(const float4*)&Bs[kk][tx * 8 + 4];
            a[0]=a0.x;a[1]=a0.y;a[2]=a0.z;a[3]=a0.w;a[4]=a1.x;a[5]=a1.y;a[6]=a1.z;a[7]=a1.w;
            bb[0]=b0.x;bb[1]=b0.y;bb[2]=b0.z;bb[3]=b0.w;bb[4]=b1.x;bb[5]=b1.y;bb[6]=b1.z;bb[7]=b1.w;
            #pragma unroll
            for (int i = 0; i < 8; i++)
                #pragma unroll
                for (int j = 0; j < 8; j++)
                    acc[i][j] = fmaf(a[i], bb[j], acc[i][j]);
        }
        __syncthreads();
    }
    int m0 = rowBase + ty * 8, n0 = colBase + tx * 8;
    float bv[8];
    #pragma unroll
    for (int j = 0; j < 8; j++) bv[j] = bias[n0 + j];
    #pragma unroll
    for (int i = 0; i < 8; i++) {
        float* crow = C + (size_t)(m0 + i) * N + n0;
        #pragma unroll
        for (int j = 0; j < 8; j++) crow[j] = acc[i][j] + bv[j];
    }
}

// ---------------------------------------------------------------------------
// bf16x3 GEMM via mma.sync.m16n8k16 (HMMA), cp.async double buffered.
// Block tile 128x128, K-chunk 32, 8 warps (warp tile 32x64).
// A splits: [m][512] bf16.  B splits: [n][512] bf16 (k contiguous = col-major).
// ---------------------------------------------------------------------------
#define TBM 128
#define TBN 128
#define TBK 32
#define NCH (DH / TBK)      // 16
// per-buffer smem offsets (each region 128 rows x 64B = 8KB)
#define SA_H 0
#define SA_L 8192
#define SB_H 16384
#define SB_L 24576
#define BUFSZ 32768
#define SMEMSZ (2 * BUFSZ)  // 64KB

// swizzled byte offset of 16B chunk `ch` (0..3) in row `r`
#define SWOFF(r, ch) ((uint32_t)((r) * 64 + 16 * ((ch) ^ (((r) >> 1) & 3))))

template <bool ACCUM, bool WF32, bool WSPLIT>
__global__ void __launch_bounds__(256, 1)
gemm_tc_kernel(const bf16* __restrict__ Ah, const bf16* __restrict__ Al,
               const bf16* __restrict__ Bh, const bf16* __restrict__ Bl,
               const float* __restrict__ bias, float* __restrict__ Cf,
               bf16* __restrict__ Oh, bf16* __restrict__ Ol) {
    extern __shared__ char smem[];
    const uint32_t sbase = smem_u32(smem);
    const int tid = threadIdx.x;
    const int lane = tid & 31;
    const int wid = tid >> 5;
    const int wm = wid & 3;          // warp row group (32 rows)
    const int wn = wid >> 2;         // warp col group (64 cols)
    const int m0 = blockIdx.y * TBM;
    const int n0 = blockIdx.x * TBN;

    const bf16* pAh = Ah + (size_t)m0 * DH;
    const bf16* pAl = Al + (size_t)m0 * DH;
    const bf16* pBh = Bh + (size_t)n0 * DH;
    const bf16* pBl = Bl + (size_t)n0 * DH;

    float acc[2][8][4];
    #pragma unroll
    for (int t = 0; t < 2; t++)
        #pragma unroll
        for (int j = 0; j < 8; j++)
            #pragma unroll
            for (int q = 0; q < 4; q++) acc[t][j][q] = 0.0f;

    // ---- async tile loader: 512 16B lines per split, 2 per thread ----
    auto load_chunk = [&](int c, int buf) {
        const uint32_t bb = sbase + buf * BUFSZ;
        const int k0 = c * TBK;
        #pragma unroll
        for (int i = 0; i < 2; i++) {
            int idx = tid + i * 256;
            int row = idx >> 2, ch = idx & 3;
            uint32_t so = SWOFF(row, ch);
            size_t go = (size_t)row * DH + k0 + ch * 8;
            cp16(bb + SA_H + so, pAh + go);
            cp16(bb + SA_L + so, pAl + go);
            cp16(bb + SB_H + so, pBh + go);
            cp16(bb + SB_L + so, pBl + go);
        }
    };

    load_chunk(0, 0);
    CP_COMMIT();

    for (int c = 0; c < NCH; c++) {
        if (c + 1 < NCH) {
            load_chunk(c + 1, (c + 1) & 1);
            CP_COMMIT();
            CP_WAIT(1);
        } else {
            CP_WAIT(0);
        }
        __syncthreads();

        const uint32_t bb = sbase + (c & 1) * BUFSZ;
        #pragma unroll
        for (int s = 0; s < 2; s++) {            // two k16 steps per chunk
            uint32_t ah[2][4], al[2][4], bh[8][2], bl[8][2];
            #pragma unroll
            for (int t = 0; t < 2; t++) {
                int r = wm * 32 + t * 16 + (lane & 15);
                int ch = 2 * s + (lane >> 4);
                uint32_t a = bb + SWOFF(r, ch);
                ldsm_x4(ah[t][0], ah[t][1], ah[t][2], ah[t][3], a + SA_H);
                ldsm_x4(al[t][0], al[t][1], al[t][2], al[t][3], a + SA_L);
            }
            #pragma unroll
            for (int p = 0; p < 4; p++) {
                int nr = wn * 64 + p * 16 + (lane & 7) + ((lane >> 4) << 3);
                int ch = 2 * s + ((lane >> 3) & 1);
                uint32_t a = bb + SB_H + SWOFF(nr, ch);
                ldsm_x4(bh[2 * p][0], bh[2 * p][1], bh[2 * p + 1][0], bh[2 * p + 1][1], a);
                ldsm_x4(bl[2 * p][0], bl[2 * p][1], bl[2 * p + 1][0], bl[2 * p + 1][1], a + 8192);
            }
            #pragma unroll
            for (int t = 0; t < 2; t++)
                #pragma unroll
                for (int j = 0; j < 8; j++) {
                    mma_bf16(acc[t][j], ah[t], bh[j]);
                    mma_bf16(acc[t][j], ah[t], bl[j]);
                    mma_bf16(acc[t][j], al[t], bh[j]);
                }
        }
        __syncthreads();
    }

    // ---- epilogue ----
    #pragma unroll
    for (int t = 0; t < 2; t++) {
        #pragma unroll
        for (int half = 0; half < 2; half++) {
            int m = m0 + wm * 32 + t * 16 + half * 8 + (lane >> 2);
            float* crow = Cf ? (Cf + (size_t)m * DH) : nullptr;
            #pragma unroll
            for (int j = 0; j < 8; j++) {
                int col = n0 + wn * 64 + j * 8 + (lane & 3) * 2;
                float v0 = acc[t][j][half * 2 + 0] + bias[col];
                float v1 = acc[t][j][half * 2 + 1] + bias[col + 1];
                if (ACCUM) {
                    float2 o = *(const float2*)(crow + col);
                    v0 += o.x; v1 += o.y;
                }
                if (WF32) *(float2*)(crow + col) = make_float2(v0, v1);
                if (WSPLIT) {
                    float r0 = fmaxf(v0, 0.0f), r1 = fmaxf(v1, 0.0f);
                    bf16 h0 = __float2bfloat16(r0), h1 = __float2bfloat16(r1);
                    bf16 l0 = __float2bfloat16(r0 - __bfloat162float(h0));
                    bf16 l1 = __float2bfloat16(r1 - __bfloat162float(h1));
                    size_t oo = (size_t)m * DH + col;
                    *(bf162*)(Oh + oo) = bf162{h0, h1};
                    *(bf162*)(Ol + oo) = bf162{l0, l1};
                }
            }
        }
    }
}

// ---------------------------------------------------------------------------
// sigma = exp(relu(h) @ w_out + b_out), one warp per point
// ---------------------------------------------------------------------------
__global__ void sigma_kernel(const float* __restrict__ w_out,
                             const float* __restrict__ b_out,
                             float* __restrict__ out) {
    int gtid = blockIdx.x * blockDim.x + threadIdx.x;
    int n = gtid >> 5, lane = gtid & 31;
    if (n >= NPTS) return;
    const float* hrow = g_h + (size_t)n * DH;
    float s = 0.0f;
    #pragma unroll
    for (int k = lane; k < DH; k += 32)
        s = fmaf(fmaxf(hrow[k], 0.0f), w_out[k], s);
    #pragma unroll
    for (int off = 16; off > 0; off >>= 1)
        s += __shfl_down_sync(0xFFFFFFFF, s, off);
    if (lane == 0) out[n] = expf(s + b_out[0]);
}

// ---------------------------------------------------------------------------
// Launch
// ---------------------------------------------------------------------------
template <typename T>
static T* sym(const T& s) {
    void* p = nullptr;
    cudaGetSymbolAddress(&p, s);
    return (T*)p;
}

extern "C" void kernel_launch(void* const* d_in, const int* in_sizes, int n_in,
                              void* d_out, int out_size) {
    const float* world_xyz = (const float*)d_in[0];
    const float* c2w       = (const float*)d_in[1];
    const float* k_mat     = (const float*)d_in[2];
    const float* features  = (const float*)d_in[3];
    const float* lin_in_w  = (const float*)d_in[4];
    const float* lin_in_b  = (const float*)d_in[5];
    const float* lin_z_w   = (const float*)d_in[6];
    const float* lin_z_b   = (const float*)d_in[7];
    const float* fc0_w     = (const float*)d_in[8];
    const float* fc0_b     = (const float*)d_in[9];
    const float* fc1_w     = (const float*)d_in[10];
    const float* fc1_b     = (const float*)d_in[11];
    const float* lin_out_w = (const float*)d_in[12];
    const float* lin_out_b = (const float*)d_in[13];
    float* out = (float*)d_out;

    cudaFuncSetAttribute(gemm_tc_kernel<true,  true,  true >, cudaFuncAttributeMaxDynamicSharedMemorySize, SMEMSZ);
    cudaFuncSetAttribute(gemm_tc_kernel<false, false, true >, cudaFuncAttributeMaxDynamicSharedMemorySize, SMEMSZ);
    cudaFuncSetAttribute(gemm_tc_kernel<true,  true,  false>, cudaFuncAttributeMaxDynamicSharedMemorySize, SMEMSZ);

    float* p_enc = (float*)sym(g_enc);
    float* p_h   = (float*)sym(g_h);
    float* p_win = (float*)sym(g_win);
    bf16* p_alh = (bf16*)sym(g_alh); bf16* p_all = (bf16*)sym(g_all);
    bf16* p_th  = (bf16*)sym(g_th);  bf16* p_tl  = (bf16*)sym(g_tl);
    bf16* p_uh  = (bf16*)sym(g_uh);  bf16* p_ul  = (bf16*)sym(g_ul);
    bf16* p_wzh = (bf16*)sym(g_wzh); bf16* p_wzl = (bf16*)sym(g_wzl);
    bf16* p_w0h = (bf16*)sym(g_w0h); bf16* p_w0l = (bf16*)sym(g_w0l);
    bf16* p_w1h = (bf16*)sym(g_w1h); bf16* p_w1l = (bf16*)sym(g_w1l);

    pad_win_kernel<<<(DENC * DH + 255) / 256, 256>>>(lin_in_w);
    enc_kernel<<<(NPTS + 255) / 256, 256>>>(world_xyz, c2w, k_mat);
    bilinear_kernel<<<NPTS, 256>>>(features);

    int wtot = NBLK * DH * DH;
    conv_w_kernel<<<(wtot + 255) / 256, 256>>>(lin_z_w, p_wzh, p_wzl, wtot);
    conv_w_kernel<<<(wtot + 255) / 256, 256>>>(fc0_w,   p_w0h, p_w0l, wtot);
    conv_w_kernel<<<(wtot + 255) / 256, 256>>>(fc1_w,   p_w1h, p_w1l, wtot);

    // h = enc @ win + b (fp32 FFMA, K=64)
    gemm_in_kernel<<<dim3(DH / 128, NPTS / 128), 256>>>(p_enc, p_win, lin_in_b,
                                                        p_h, NPTS, DH, DENC);

    dim3 grid(DH / TBN, NPTS / TBM);   // (4, 768)
    for (int i = 0; i < NBLK; i++) {
        size_t wo = (size_t)i * DH * DH;
        // h += aligned @ Wz + bz ;  th/tl = split(relu(h))
        gemm_tc_kernel<true, true, true><<<grid, 256, SMEMSZ>>>(
            p_alh, p_all, p_wzh + wo, p_wzl + wo, lin_z_b + (size_t)i * DH,
            p_h, p_th, p_tl);
        // net = relu(h) @ W0 + b0 ;  uh/ul = split(relu(net))
        gemm_tc_kernel<false, false, true><<<grid, 256, SMEMSZ>>>(
            p_th, p_tl, p_w0h + wo, p_w0l + wo, fc0_b + (size_t)i * DH,
            nullptr, p_uh, p_ul);
        // h += relu(net) @ W1 + b1
        gemm_tc_kernel<true, true, false><<<grid, 256, SMEMSZ>>>(
            p_uh, p_ul, p_w1h + wo, p_w1l + wo, fc1_b + (size_t)i * DH,
            p_h, nullptr, nullptr);
    }

    sigma_kernel<<<(NPTS * 32 + 255) / 256, 256>>>(lin_out_w, lin_out_b, out);
}

// round 6
// speedup vs baseline: 3.1346x; 1.5596x over previous
#include <cuda_runtime.h>
#include <cuda_fp16.h>
#include <cstdint>
#include <math.h>

// ---------------------------------------------------------------------------
// Problem constants
// ---------------------------------------------------------------------------
#define NPTS      98304
#define NPB       49152
#define DH        512
#define NBLK      5
#define NFREQ     10
#define IMGH      128
#define IMGW      128
#define DENC      64

// ---------------------------------------------------------------------------
// Scratch
// ---------------------------------------------------------------------------
__device__ float g_enc[NPTS * DENC];
__device__ float g_uv[NPTS * 2];
__device__ float g_h[NPTS * DH];            // fp32 residual stream
__device__ float g_win[DENC * DH];
// fp16 hi/lo activation splits
__device__ __half g_alh[NPTS * DH];
__device__ __half g_all[NPTS * DH];
__device__ __half g_th[NPTS * DH];
__device__ __half g_tl[NPTS * DH];
__device__ __half g_uh[NPTS * DH];
__device__ __half g_ul[NPTS * DH];
// transposed single-fp16 weights [l][n][k]
__device__ __half g_wz[NBLK * DH * DH];
__device__ __half g_w0[NBLK * DH * DH];
__device__ __half g_w1[NBLK * DH * DH];

// ---------------------------------------------------------------------------
// PTX helpers (baseline ISA: mma.sync / ldmatrix / cp.async)
// ---------------------------------------------------------------------------
__device__ __forceinline__ uint32_t smem_u32(const void* p) {
    uint32_t a;
    asm("{ .reg .u64 t; cvta.to.shared.u64 t, %1; cvt.u32.u64 %0, t; }" : "=r"(a) : "l"(p));
    return a;
}
__device__ __forceinline__ void ldsm_x4(uint32_t& r0, uint32_t& r1, uint32_t& r2,
                                        uint32_t& r3, uint32_t addr) {
    asm volatile("ldmatrix.sync.aligned.m8n8.x4.shared.b16 {%0,%1,%2,%3}, [%4];"
                 : "=r"(r0), "=r"(r1), "=r"(r2), "=r"(r3) : "r"(addr));
}
__device__ __forceinline__ void mma_f16(float* d, const uint32_t* a, const uint32_t* b) {
    asm volatile(
        "mma.sync.aligned.m16n8k16.row.col.f32.f16.f16.f32 "
        "{%0,%1,%2,%3}, {%4,%5,%6,%7}, {%8,%9}, {%0,%1,%2,%3};"
        : "+f"(d[0]), "+f"(d[1]), "+f"(d[2]), "+f"(d[3])
        : "r"(a[0]), "r"(a[1]), "r"(a[2]), "r"(a[3]), "r"(b[0]), "r"(b[1]));
}
__device__ __forceinline__ void cp16(uint32_t dst, const void* src) {
    asm volatile("cp.async.cg.shared.global [%0], [%1], 16;" :: "r"(dst), "l"(src));
}
#define CP_COMMIT() asm volatile("cp.async.commit_group;" ::: "memory")
#define CP_WAIT(n)  asm volatile("cp.async.wait_group %0;" :: "n"(n) : "memory")

// ---------------------------------------------------------------------------
// Small prep kernels
// ---------------------------------------------------------------------------
__global__ void pad_win_kernel(const float* __restrict__ w) {
    int t = blockIdx.x * blockDim.x + threadIdx.x;
    if (t >= DENC * DH) return;
    int k = t / DH;
    g_win[t] = (k < 63) ? w[t] : 0.0f;
}

__global__ void enc_kernel(const float* __restrict__ xyz,
                           const float* __restrict__ c2w,
                           const float* __restrict__ kmat) {
    int n = blockIdx.x * blockDim.x + threadIdx.x;
    if (n >= NPTS) return;
    int b = n / NPB;
    float p0 = xyz[n * 3 + 0], p1 = xyz[n * 3 + 1], p2 = xyz[n * 3 + 2];
    const float* M = c2w + b * 16;
    float q0 = p0 - M[3], q1 = p1 - M[7], q2 = p2 - M[11];
    float cam[3];
    #pragma unroll
    for (int i = 0; i < 3; i++)
        cam[i] = M[0 * 4 + i] * q0 + M[1 * 4 + i] * q1 + M[2 * 4 + i] * q2;
    const float* K = kmat + b * 9;
    float uw = K[0] * cam[0] + K[1] * cam[1] + K[2] * cam[2];
    float vw = K[3] * cam[0] + K[4] * cam[1] + K[5] * cam[2];
    float zw = K[6] * cam[0] + K[7] * cam[1] + K[8] * cam[2];
    float z = (fabsf(zw) < 1e-6f) ? 1e-6f : zw;
    g_uv[n * 2 + 0] = uw / z;
    g_uv[n * 2 + 1] = vw / z;
    float* E = g_enc + (size_t)n * DENC;
    E[0] = cam[0]; E[1] = cam[1]; E[2] = cam[2];
    const float TWO_PI = 6.283185307179586f;
    #pragma unroll
    for (int axis = 0; axis < 3; axis++)
        #pragma unroll
        for (int f = 0; f < NFREQ; f++) {
            float s = TWO_PI * cam[axis] * (float)(1 << f);
            E[3  + axis * NFREQ + f] = sinf(s);
            E[33 + axis * NFREQ + f] = cosf(s);
        }
    E[63] = 0.0f;
}

// bilinear gather -> fp16 hi/lo split
__global__ void bilinear_kernel(const float* __restrict__ feat) {
    int n = blockIdx.x;
    int b = n / NPB;
    float u = g_uv[n * 2 + 0], v = g_uv[n * 2 + 1];
    float x = fminf(fmaxf(u, 0.0f), (float)(IMGW - 1));
    float y = fminf(fmaxf(v, 0.0f), (float)(IMGH - 1));
    float x0 = floorf(x), y0 = floorf(y);
    int x0i = (int)x0, y0i = (int)y0;
    int x1i = min(x0i + 1, IMGW - 1);
    int y1i = min(y0i + 1, IMGH - 1);
    float wx = x - x0, wy = y - y0;
    float w00 = (1.0f - wx) * (1.0f - wy);
    float w01 = wx * (1.0f - wy);
    float w10 = (1.0f - wx) * wy;
    float w11 = wx * wy;
    const float* fb = feat + (size_t)b * DH * IMGH * IMGW;
    int o00 = y0i * IMGW + x0i, o01 = y0i * IMGW + x1i;
    int o10 = y1i * IMGW + x0i, o11 = y1i * IMGW + x1i;
    size_t base = (size_t)n * DH;
    for (int c = threadIdx.x; c < DH; c += blockDim.x) {
        const float* fp = fb + (size_t)c * (IMGH * IMGW);
        float r = fp[o00] * w00 + fp[o01] * w01 + fp[o10] * w10 + fp[o11] * w11;
        __half hi = __float2half_rn(r);
        __half lo = __float2half_rn(r - __half2float(hi));
        g_alh[base + c] = hi;
        g_all[base + c] = lo;
    }
}

// weights: W[l][k][n] fp32 -> single fp16 [l][n][k] (transposed)
__global__ void conv_w_kernel(const float* __restrict__ W, __half* __restrict__ O,
                              int total) {
    int idx = blockIdx.x * blockDim.x + threadIdx.x;
    if (idx >= total) return;
    int l = idx >> 18;
    int rem = idx & 262143;
    int k = rem >> 9;
    int n = rem & 511;
    O[(l << 18) + n * DH + k] = __float2half_rn(W[idx]);
}

// ---------------------------------------------------------------------------
// FFMA GEMM for the K=64 input layer (h = enc @ win + b)
// ---------------------------------------------------------------------------
__global__ void __launch_bounds__(256, 2)
gemm_in_kernel(const float* __restrict__ A, const float* __restrict__ B,
               const float* __restrict__ bias, float* __restrict__ C,
               int M, int N, int K) {
    const int BM = 128, BN = 128, BK = 16;
    __shared__ float As[BK][BM + 4];
    __shared__ float Bs[BK][BN];
    int tid = threadIdx.x;
    int tx = tid & 15, ty = tid >> 4;
    int rowBase = blockIdx.y * BM, colBase = blockIdx.x * BN;
    int a_row = tid >> 2, a_kc = (tid & 3) * 4;
    int b_kr = tid >> 5, b_nc = (tid & 31) * 4;
    float acc[8][8];
    #pragma unroll
    for (int i = 0; i < 8; i++)
        #pragma unroll
        for (int j = 0; j < 8; j++) acc[i][j] = 0.0f;
    for (int k0 = 0; k0 < K; k0 += BK) {
        #pragma unroll
        for (int pass = 0; pass < 2; pass++) {
            int m = a_row + pass * 64;
            const float4 v = *(const float4*)(A + (size_t)(rowBase + m) * K + k0 + a_kc);
            As[a_kc + 0][m] = v.x; As[a_kc + 1][m] = v.y;
            As[a_kc + 2][m] = v.z; As[a_kc + 3][m] = v.w;
        }
        #pragma unroll
        for (int pass = 0; pass < 2; pass++) {
            int kr = b_kr + pass * 8;
            *(float4*)&Bs[kr][b_nc] = *(const float4*)(B + (size_t)(k0 + kr) * N + colBase + b_nc);
        }
        __syncthreads();
        #pragma unroll
        for (int kk = 0; kk < BK; kk++) {
            float a[8], bb[8];
            float4 a0 = *(const float4*)&As[kk][ty * 8];
            float4 a1 = *(const float4*)&As[kk][ty * 8 + 4];
            float4 b0 = *(const float4*)&Bs[kk][tx * 8];
            float4 b1 = *(const float4*)&Bs[kk][tx * 8 + 4];
            a[0]=a0.x;a[1]=a0.y;a[2]=a0.z;a[3]=a0.w;a[4]=a1.x;a[5]=a1.y;a[6]=a1.z;a[7]=a1.w;
            bb[0]=b0.x;bb[1]=b0.y;bb[2]=b0.z;bb[3]=b0.w;bb[4]=b1.x;bb[5]=b1.y;bb[6]=b1.z;bb[7]=b1.w;
            #pragma unroll
            for (int i = 0; i < 8; i++)
                #pragma unroll
                for (int j = 0; j < 8; j++)
                    acc[i][j] = fmaf(a[i], bb[j], acc[i][j]);
        }
        __syncthreads();
    }
    int m0 = rowBase + ty * 8, n0 = colBase + tx * 8;
    float bv[8];
    #pragma unroll
    for (int j = 0; j < 8; j++) bv[j] = bias[n0 + j];
    #pragma unroll
    for (int i = 0; i < 8; i++) {
        float* crow = C + (size_t)(m0 + i) * N + n0;
        #pragma unroll
        for (int j = 0; j < 8; j++) crow[j] = acc[i][j] + bv[j];
    }
}

// ---------------------------------------------------------------------------
// fp16x2 GEMM via mma.sync.m16n8k16 (HMMA), cp.async double buffered.
// Block tile 128x128, K-chunk 32, 8 warps (warp tile 32x64).
// A splits: [m][512] fp16 hi/lo.  B: [n][512] fp16 (k contiguous = col-major).
// 2 passes: acc += ah*B ; acc += al*B.
// ---------------------------------------------------------------------------
#define TBM 128
#define TBN 128
#define TBK 32
#define NCH (DH / TBK)      // 16
// per-buffer smem offsets (each region 128 rows x 64B = 8KB)
#define SA_H 0
#define SA_L 8192
#define SB   16384
#define BUFSZ 24576
#define SMEMSZ (2 * BUFSZ)  // 48KB

// swizzled byte offset of 16B chunk `ch` (0..3) in row `r`
#define SWOFF(r, ch) ((uint32_t)((r) * 64 + 16 * ((ch) ^ (((r) >> 1) & 3))))

template <bool ACCUM, bool WF32, bool WSPLIT>
__global__ void __launch_bounds__(256, 2)
gemm_tc_kernel(const __half* __restrict__ Ah, const __half* __restrict__ Al,
               const __half* __restrict__ Bw,
               const float* __restrict__ bias, float* __restrict__ Cf,
               __half* __restrict__ Oh, __half* __restrict__ Ol) {
    extern __shared__ char smem[];
    const uint32_t sbase = smem_u32(smem);
    const int tid = threadIdx.x;
    const int lane = tid & 31;
    const int wid = tid >> 5;
    const int wm = wid & 3;          // warp row group (32 rows)
    const int wn = wid >> 2;         // warp col group (64 cols)
    const int m0 = blockIdx.y * TBM;
    const int n0 = blockIdx.x * TBN;

    const __half* pAh = Ah + (size_t)m0 * DH;
    const __half* pAl = Al + (size_t)m0 * DH;
    const __half* pB  = Bw + (size_t)n0 * DH;

    float acc[2][8][4];
    #pragma unroll
    for (int t = 0; t < 2; t++)
        #pragma unroll
        for (int j = 0; j < 8; j++)
            #pragma unroll
            for (int q = 0; q < 4; q++) acc[t][j][q] = 0.0f;

    // ---- async tile loader: 1536 16B lines, 6 per thread ----
    auto load_chunk = [&](int c, int buf) {
        const uint32_t bb = sbase + buf * BUFSZ;
        const int k0 = c * TBK;
        #pragma unroll
        for (int i = 0; i < 2; i++) {
            int idx = tid + i * 256;
            int row = idx >> 2, ch = idx & 3;
            uint32_t so = SWOFF(row, ch);
            size_t go = (size_t)row * DH + k0 + ch * 8;
            cp16(bb + SA_H + so, pAh + go);
            cp16(bb + SA_L + so, pAl + go);
            cp16(bb + SB   + so, pB  + go);
        }
    };

    load_chunk(0, 0);
    CP_COMMIT();

    for (int c = 0; c < NCH; c++) {
        if (c + 1 < NCH) {
            load_chunk(c + 1, (c + 1) & 1);
            CP_COMMIT();
            CP_WAIT(1);
        } else {
            CP_WAIT(0);
        }
        __syncthreads();

        const uint32_t bb = sbase + (c & 1) * BUFSZ;
        #pragma unroll
        for (int s = 0; s < 2; s++) {            // two k16 steps per chunk
            uint32_t ah[2][4], al[2][4], bh[8][2];
            #pragma unroll
            for (int t = 0; t < 2; t++) {
                int r = wm * 32 + t * 16 + (lane & 15);
                int ch = 2 * s + (lane >> 4);
                uint32_t a = bb + SWOFF(r, ch);
                ldsm_x4(ah[t][0], ah[t][1], ah[t][2], ah[t][3], a + SA_H);
                ldsm_x4(al[t][0], al[t][1], al[t][2], al[t][3], a + SA_L);
            }
            #pragma unroll
            for (int p = 0; p < 4; p++) {
                int nr = wn * 64 + p * 16 + (lane & 7) + ((lane >> 4) << 3);
                int ch = 2 * s + ((lane >> 3) & 1);
                uint32_t a = bb + SB + SWOFF(nr, ch);
                ldsm_x4(bh[2 * p][0], bh[2 * p][1], bh[2 * p + 1][0], bh[2 * p + 1][1], a);
            }
            #pragma unroll
            for (int t = 0; t < 2; t++)
                #pragma unroll
                for (int j = 0; j < 8; j++) {
                    mma_f16(acc[t][j], ah[t], bh[j]);
                    mma_f16(acc[t][j], al[t], bh[j]);
                }
        }
        __syncthreads();
    }

    // ---- epilogue ----
    #pragma unroll
    for (int t = 0; t < 2; t++) {
        #pragma unroll
        for (int half = 0; half < 2; half++) {
            int m = m0 + wm * 32 + t * 16 + half * 8 + (lane >> 2);
            float* crow = (WF32 || ACCUM) ? (Cf + (size_t)m * DH) : nullptr;
            #pragma unroll
            for (int j = 0; j < 8; j++) {
                int col = n0 + wn * 64 + j * 8 + (lane & 3) * 2;
                float v0 = acc[t][j][half * 2 + 0] + bias[col];
                float v1 = acc[t][j][half * 2 + 1] + bias[col + 1];
                if (ACCUM) {
                    float2 o = *(const float2*)(crow + col);
                    v0 += o.x; v1 += o.y;
                }
                if (WF32) *(float2*)(crow + col) = make_float2(v0, v1);
                if (WSPLIT) {
                    float r0 = fmaxf(v0, 0.0f), r1 = fmaxf(v1, 0.0f);
                    __half h0 = __float2half_rn(r0), h1 = __float2half_rn(r1);
                    __half l0 = __float2half_rn(r0 - __half2float(h0));
                    __half l1 = __float2half_rn(r1 - __half2float(h1));
                    size_t oo = (size_t)m * DH + col;
                    *(__half2*)(Oh + oo) = __half2{h0, h1};
                    *(__half2*)(Ol + oo) = __half2{l0, l1};
                }
            }
        }
    }
}

// ---------------------------------------------------------------------------
// sigma = exp(relu(h) @ w_out + b_out), one warp per point
// ---------------------------------------------------------------------------
__global__ void sigma_kernel(const float* __restrict__ w_out,
                             const float* __restrict__ b_out,
                             float* __restrict__ out) {
    int gtid = blockIdx.x * blockDim.x + threadIdx.x;
    int n = gtid >> 5, lane = gtid & 31;
    if (n >= NPTS) return;
    const float* hrow = g_h + (size_t)n * DH;
    float s = 0.0f;
    #pragma unroll
    for (int k = lane; k < DH; k += 32)
        s = fmaf(fmaxf(hrow[k], 0.0f), w_out[k], s);
    #pragma unroll
    for (int off = 16; off > 0; off >>= 1)
        s += __shfl_down_sync(0xFFFFFFFF, s, off);
    if (lane == 0) out[n] = expf(s + b_out[0]);
}

// ---------------------------------------------------------------------------
// Launch
// ---------------------------------------------------------------------------
template <typename T>
static T* sym(const T& s) {
    void* p = nullptr;
    cudaGetSymbolAddress(&p, s);
    return (T*)p;
}

extern "C" void kernel_launch(void* const* d_in, const int* in_sizes, int n_in,
                              void* d_out, int out_size) {
    const float* world_xyz = (const float*)d_in[0];
    const float* c2w       = (const float*)d_in[1];
    const float* k_mat     = (const float*)d_in[2];
    const float* features  = (const float*)d_in[3];
    const float* lin_in_w  = (const float*)d_in[4];
    const float* lin_in_b  = (const float*)d_in[5];
    const float* lin_z_w   = (const float*)d_in[6];
    const float* lin_z_b   = (const float*)d_in[7];
    const float* fc0_w     = (const float*)d_in[8];
    const float* fc0_b     = (const float*)d_in[9];
    const float* fc1_w     = (const float*)d_in[10];
    const float* fc1_b     = (const float*)d_in[11];
    const float* lin_out_w = (const float*)d_in[12];
    const float* lin_out_b = (const float*)d_in[13];
    float* out = (float*)d_out;

    cudaFuncSetAttribute(gemm_tc_kernel<true,  true,  true >, cudaFuncAttributeMaxDynamicSharedMemorySize, SMEMSZ);
    cudaFuncSetAttribute(gemm_tc_kernel<false, false, true >, cudaFuncAttributeMaxDynamicSharedMemorySize, SMEMSZ);
    cudaFuncSetAttribute(gemm_tc_kernel<true,  true,  false>, cudaFuncAttributeMaxDynamicSharedMemorySize, SMEMSZ);

    float* p_enc = (float*)sym(g_enc);
    float* p_h   = (float*)sym(g_h);
    float* p_win = (float*)sym(g_win);
    __half* p_alh = (__half*)sym(g_alh); __half* p_all = (__half*)sym(g_all);
    __half* p_th  = (__half*)sym(g_th);  __half* p_tl  = (__half*)sym(g_tl);
    __half* p_uh  = (__half*)sym(g_uh);  __half* p_ul  = (__half*)sym(g_ul);
    __half* p_wz  = (__half*)sym(g_wz);
    __half* p_w0  = (__half*)sym(g_w0);
    __half* p_w1  = (__half*)sym(g_w1);

    pad_win_kernel<<<(DENC * DH + 255) / 256, 256>>>(lin_in_w);
    enc_kernel<<<(NPTS + 255) / 256, 256>>>(world_xyz, c2w, k_mat);
    bilinear_kernel<<<NPTS, 256>>>(features);

    int wtot = NBLK * DH * DH;
    conv_w_kernel<<<(wtot + 255) / 256, 256>>>(lin_z_w, p_wz, wtot);
    conv_w_kernel<<<(wtot + 255) / 256, 256>>>(fc0_w,   p_w0, wtot);
    conv_w_kernel<<<(wtot + 255) / 256, 256>>>(fc1_w,   p_w1, wtot);

    // h = enc @ win + b (fp32 FFMA, K=64)
    gemm_in_kernel<<<dim3(DH / 128, NPTS / 128), 256>>>(p_enc, p_win, lin_in_b,
                                                        p_h, NPTS, DH, DENC);

    dim3 grid(DH / TBN, NPTS / TBM);   // (4, 768)
    for (int i = 0; i < NBLK; i++) {
        size_t wo = (size_t)i * DH * DH;
        // h += aligned @ Wz + bz ;  th/tl = split(relu(h))
        gemm_tc_kernel<true, true, true><<<grid, 256, SMEMSZ>>>(
            p_alh, p_all, p_wz + wo, lin_z_b + (size_t)i * DH,
            p_h, p_th, p_tl);
        // net = relu(h) @ W0 + b0 ;  uh/ul = split(relu(net))
        gemm_tc_kernel<false, false, true><<<grid, 256, SMEMSZ>>>(
            p_th, p_tl, p_w0 + wo, fc0_b + (size_t)i * DH,
            nullptr, p_uh, p_ul);
        // h += relu(net) @ W1 + b1
        gemm_tc_kernel<true, true, false><<<grid, 256, SMEMSZ>>>(
            p_uh, p_ul, p_w1 + wo, fc1_b + (size_t)i * DH,
            p_h, nullptr, nullptr);
    }

    sigma_kernel<<<(NPTS * 32 + 255) / 256, 256>>>(lin_out_w, lin_out_b, out);
}

// round 7
// speedup vs baseline: 4.3752x; 1.3958x over previous
#include <cuda_runtime.h>
#include <cuda_fp16.h>
#include <cstdint>
#include <math.h>

// ---------------------------------------------------------------------------
// Problem constants
// ---------------------------------------------------------------------------
#define NPTS      98304
#define NPB       49152
#define DH        512
#define NBLK      5
#define NFREQ     10
#define IMGH      128
#define IMGW      128
#define DENC      64

// ---------------------------------------------------------------------------
// Scratch
// ---------------------------------------------------------------------------
__device__ float g_enc[NPTS * DENC];
__device__ float g_uv[NPTS * 2];
__device__ float g_h[NPTS * DH];            // fp32 residual stream
__device__ float g_win[DENC * DH];
// fp16 activations
__device__ __half g_al[NPTS * DH];          // aligned features
__device__ __half g_t[NPTS * DH];           // relu(h)
__device__ __half g_u[NPTS * DH];           // relu(net)
// transposed fp16 weights [l][n][k]
__device__ __half g_wz[NBLK * DH * DH];
__device__ __half g_w0[NBLK * DH * DH];
__device__ __half g_w1[NBLK * DH * DH];

// ---------------------------------------------------------------------------
// PTX helpers (baseline ISA: mma.sync / ldmatrix / cp.async)
// ---------------------------------------------------------------------------
__device__ __forceinline__ uint32_t smem_u32(const void* p) {
    uint32_t a;
    asm("{ .reg .u64 t; cvta.to.shared.u64 t, %1; cvt.u32.u64 %0, t; }" : "=r"(a) : "l"(p));
    return a;
}
__device__ __forceinline__ void ldsm_x4(uint32_t& r0, uint32_t& r1, uint32_t& r2,
                                        uint32_t& r3, uint32_t addr) {
    asm volatile("ldmatrix.sync.aligned.m8n8.x4.shared.b16 {%0,%1,%2,%3}, [%4];"
                 : "=r"(r0), "=r"(r1), "=r"(r2), "=r"(r3) : "r"(addr));
}
__device__ __forceinline__ void mma_f16(float* d, const uint32_t* a, const uint32_t* b) {
    asm volatile(
        "mma.sync.aligned.m16n8k16.row.col.f32.f16.f16.f32 "
        "{%0,%1,%2,%3}, {%4,%5,%6,%7}, {%8,%9}, {%0,%1,%2,%3};"
        : "+f"(d[0]), "+f"(d[1]), "+f"(d[2]), "+f"(d[3])
        : "r"(a[0]), "r"(a[1]), "r"(a[2]), "r"(a[3]), "r"(b[0]), "r"(b[1]));
}
__device__ __forceinline__ void cp16(uint32_t dst, const void* src) {
    asm volatile("cp.async.cg.shared.global [%0], [%1], 16;" :: "r"(dst), "l"(src));
}
#define CP_COMMIT() asm volatile("cp.async.commit_group;" ::: "memory")
#define CP_WAIT(n)  asm volatile("cp.async.wait_group %0;" :: "n"(n) : "memory")

// ---------------------------------------------------------------------------
// Small prep kernels
// ---------------------------------------------------------------------------
__global__ void pad_win_kernel(const float* __restrict__ w) {
    int t = blockIdx.x * blockDim.x + threadIdx.x;
    if (t >= DENC * DH) return;
    int k = t / DH;
    g_win[t] = (k < 63) ? w[t] : 0.0f;
}

__global__ void enc_kernel(const float* __restrict__ xyz,
                           const float* __restrict__ c2w,
                           const float* __restrict__ kmat) {
    int n = blockIdx.x * blockDim.x + threadIdx.x;
    if (n >= NPTS) return;
    int b = n / NPB;
    float p0 = xyz[n * 3 + 0], p1 = xyz[n * 3 + 1], p2 = xyz[n * 3 + 2];
    const float* M = c2w + b * 16;
    float q0 = p0 - M[3], q1 = p1 - M[7], q2 = p2 - M[11];
    float cam[3];
    #pragma unroll
    for (int i = 0; i < 3; i++)
        cam[i] = M[0 * 4 + i] * q0 + M[1 * 4 + i] * q1 + M[2 * 4 + i] * q2;
    const float* K = kmat + b * 9;
    float uw = K[0] * cam[0] + K[1] * cam[1] + K[2] * cam[2];
    float vw = K[3] * cam[0] + K[4] * cam[1] + K[5] * cam[2];
    float zw = K[6] * cam[0] + K[7] * cam[1] + K[8] * cam[2];
    float z = (fabsf(zw) < 1e-6f) ? 1e-6f : zw;
    g_uv[n * 2 + 0] = uw / z;
    g_uv[n * 2 + 1] = vw / z;
    float* E = g_enc + (size_t)n * DENC;
    E[0] = cam[0]; E[1] = cam[1]; E[2] = cam[2];
    const float TWO_PI = 6.283185307179586f;
    #pragma unroll
    for (int axis = 0; axis < 3; axis++)
        #pragma unroll
        for (int f = 0; f < NFREQ; f++) {
            float s = TWO_PI * cam[axis] * (float)(1 << f);
            E[3  + axis * NFREQ + f] = sinf(s);
            E[33 + axis * NFREQ + f] = cosf(s);
        }
    E[63] = 0.0f;
}

// bilinear gather -> fp16
__global__ void bilinear_kernel(const float* __restrict__ feat) {
    int n = blockIdx.x;
    int b = n / NPB;
    float u = g_uv[n * 2 + 0], v = g_uv[n * 2 + 1];
    float x = fminf(fmaxf(u, 0.0f), (float)(IMGW - 1));
    float y = fminf(fmaxf(v, 0.0f), (float)(IMGH - 1));
    float x0 = floorf(x), y0 = floorf(y);
    int x0i = (int)x0, y0i = (int)y0;
    int x1i = min(x0i + 1, IMGW - 1);
    int y1i = min(y0i + 1, IMGH - 1);
    float wx = x - x0, wy = y - y0;
    float w00 = (1.0f - wx) * (1.0f - wy);
    float w01 = wx * (1.0f - wy);
    float w10 = (1.0f - wx) * wy;
    float w11 = wx * wy;
    const float* fb = feat + (size_t)b * DH * IMGH * IMGW;
    int o00 = y0i * IMGW + x0i, o01 = y0i * IMGW + x1i;
    int o10 = y1i * IMGW + x0i, o11 = y1i * IMGW + x1i;
    size_t base = (size_t)n * DH;
    for (int c = threadIdx.x; c < DH; c += blockDim.x) {
        const float* fp = fb + (size_t)c * (IMGH * IMGW);
        float r = fp[o00] * w00 + fp[o01] * w01 + fp[o10] * w10 + fp[o11] * w11;
        g_al[base + c] = __float2half_rn(r);
    }
}

// weights: W[l][k][n] fp32 -> fp16 [l][n][k] (transposed)
__global__ void conv_w_kernel(const float* __restrict__ W, __half* __restrict__ O,
                              int total) {
    int idx = blockIdx.x * blockDim.x + threadIdx.x;
    if (idx >= total) return;
    int l = idx >> 18;
    int rem = idx & 262143;
    int k = rem >> 9;
    int n = rem & 511;
    O[(l << 18) + n * DH + k] = __float2half_rn(W[idx]);
}

// ---------------------------------------------------------------------------
// FFMA GEMM for the K=64 input layer (h = enc @ win + b)
// ---------------------------------------------------------------------------
__global__ void __launch_bounds__(256, 2)
gemm_in_kernel(const float* __restrict__ A, const float* __restrict__ B,
               const float* __restrict__ bias, float* __restrict__ C,
               int M, int N, int K) {
    const int BM = 128, BN = 128, BK = 16;
    __shared__ float As[BK][BM + 4];
    __shared__ float Bs[BK][BN];
    int tid = threadIdx.x;
    int tx = tid & 15, ty = tid >> 4;
    int rowBase = blockIdx.y * BM, colBase = blockIdx.x * BN;
    int a_row = tid >> 2, a_kc = (tid & 3) * 4;
    int b_kr = tid >> 5, b_nc = (tid & 31) * 4;
    float acc[8][8];
    #pragma unroll
    for (int i = 0; i < 8; i++)
        #pragma unroll
        for (int j = 0; j < 8; j++) acc[i][j] = 0.0f;
    for (int k0 = 0; k0 < K; k0 += BK) {
        #pragma unroll
        for (int pass = 0; pass < 2; pass++) {
            int m = a_row + pass * 64;
            const float4 v = *(const float4*)(A + (size_t)(rowBase + m) * K + k0 + a_kc);
            As[a_kc + 0][m] = v.x; As[a_kc + 1][m] = v.y;
            As[a_kc + 2][m] = v.z; As[a_kc + 3][m] = v.w;
        }
        #pragma unroll
        for (int pass = 0; pass < 2; pass++) {
            int kr = b_kr + pass * 8;
            *(float4*)&Bs[kr][b_nc] = *(const float4*)(B + (size_t)(k0 + kr) * N + colBase + b_nc);
        }
        __syncthreads();
        #pragma unroll
        for (int kk = 0; kk < BK; kk++) {
            float a[8], bb[8];
            float4 a0 = *(const float4*)&As[kk][ty * 8];
            float4 a1 = *(const float4*)&As[kk][ty * 8 + 4];
            float4 b0 = *(const float4*)&Bs[kk][tx * 8];
            float4 b1 = *(const float4*)&Bs[kk][tx * 8 + 4];
            a[0]=a0.x;a[1]=a0.y;a[2]=a0.z;a[3]=a0.w;a[4]=a1.x;a[5]=a1.y;a[6]=a1.z;a[7]=a1.w;
            bb[0]=b0.x;bb[1]=b0.y;bb[2]=b0.z;bb[3]=b0.w;bb[4]=b1.x;bb[5]=b1.y;bb[6]=b1.z;bb[7]=b1.w;
            #pragma unroll
            for (int i = 0; i < 8; i++)
                #pragma unroll
                for (int j = 0; j < 8; j++)
                    acc[i][j] = fmaf(a[i], bb[j], acc[i][j]);
        }
        __syncthreads();
    }
    int m0 = rowBase + ty * 8, n0 = colBase + tx * 8;
    float bv[8];
    #pragma unroll
    for (int j = 0; j < 8; j++) bv[j] = bias[n0 + j];
    #pragma unroll
    for (int i = 0; i < 8; i++) {
        float* crow = C + (size_t)(m0 + i) * N + n0;
        #pragma unroll
        for (int j = 0; j < 8; j++) crow[j] = acc[i][j] + bv[j];
    }
}

// ---------------------------------------------------------------------------
// fp16 single-pass GEMM via mma.sync.m16n8k16, cp.async double buffered.
// Block tile 128x128, K-chunk 32, 8 warps (warp tile 32x64).
// A: [m][512] fp16.  B: [n][512] fp16 (k contiguous = col-major).
// ---------------------------------------------------------------------------
#define TBM 128
#define TBN 128
#define TBK 32
#define NCH (DH / TBK)      // 16
// per-buffer smem: A 8KB + B 8KB
#define SA   0
#define SB   8192
#define BUFSZ 16384
#define SMEMSZ (2 * BUFSZ)  // 32KB

// swizzled byte offset of 16B chunk `ch` (0..3) in row `r`
#define SWOFF(r, ch) ((uint32_t)((r) * 64 + 16 * ((ch) ^ (((r) >> 1) & 3))))

template <bool ACCUM, bool WF32, bool WHALF>
__global__ void __launch_bounds__(256, 2)
gemm_tc_kernel(const __half* __restrict__ Aw, const __half* __restrict__ Bw,
               const float* __restrict__ bias, float* __restrict__ Cf,
               __half* __restrict__ Oh) {
    extern __shared__ char smem[];
    const uint32_t sbase = smem_u32(smem);
    const int tid = threadIdx.x;
    const int lane = tid & 31;
    const int wid = tid >> 5;
    const int wm = wid & 3;          // warp row group (32 rows)
    const int wn = wid >> 2;         // warp col group (64 cols)
    const int m0 = blockIdx.y * TBM;
    const int n0 = blockIdx.x * TBN;

    const __half* pA = Aw + (size_t)m0 * DH;
    const __half* pB = Bw + (size_t)n0 * DH;

    float acc[2][8][4];
    #pragma unroll
    for (int t = 0; t < 2; t++)
        #pragma unroll
        for (int j = 0; j < 8; j++)
            #pragma unroll
            for (int q = 0; q < 4; q++) acc[t][j][q] = 0.0f;

    // ---- async tile loader: 1024 16B lines, 4 per thread ----
    auto load_chunk = [&](int c, int buf) {
        const uint32_t bb = sbase + buf * BUFSZ;
        const int k0 = c * TBK;
        int row = tid >> 2, ch = tid & 3;
        #pragma unroll
        for (int i = 0; i < 2; i++) {
            int r = row + i * 64;
            uint32_t so = SWOFF(r, ch);
            size_t go = (size_t)r * DH + k0 + ch * 8;
            cp16(bb + SA + so, pA + go);
            cp16(bb + SB + so, pB + go);
        }
    };

    load_chunk(0, 0);
    CP_COMMIT();

    for (int c = 0; c < NCH; c++) {
        if (c + 1 < NCH) {
            load_chunk(c + 1, (c + 1) & 1);
            CP_COMMIT();
            CP_WAIT(1);
        } else {
            CP_WAIT(0);
        }
        __syncthreads();

        const uint32_t bb = sbase + (c & 1) * BUFSZ;
        #pragma unroll
        for (int s = 0; s < 2; s++) {            // two k16 steps per chunk
            uint32_t ah[2][4], bh[8][2];
            #pragma unroll
            for (int t = 0; t < 2; t++) {
                int r = wm * 32 + t * 16 + (lane & 15);
                int ch = 2 * s + (lane >> 4);
                ldsm_x4(ah[t][0], ah[t][1], ah[t][2], ah[t][3], bb + SA + SWOFF(r, ch));
            }
            #pragma unroll
            for (int p = 0; p < 4; p++) {
                int nr = wn * 64 + p * 16 + (lane & 7) + ((lane >> 4) << 3);
                int ch = 2 * s + ((lane >> 3) & 1);
                ldsm_x4(bh[2 * p][0], bh[2 * p][1], bh[2 * p + 1][0], bh[2 * p + 1][1],
                        bb + SB + SWOFF(nr, ch));
            }
            #pragma unroll
            for (int t = 0; t < 2; t++)
                #pragma unroll
                for (int j = 0; j < 8; j++)
                    mma_f16(acc[t][j], ah[t], bh[j]);
        }
        __syncthreads();
    }

    // ---- epilogue ----
    #pragma unroll
    for (int t = 0; t < 2; t++) {
        #pragma unroll
        for (int half = 0; half < 2; half++) {
            int m = m0 + wm * 32 + t * 16 + half * 8 + (lane >> 2);
            float* crow = (WF32 || ACCUM) ? (Cf + (size_t)m * DH) : nullptr;
            #pragma unroll
            for (int j = 0; j < 8; j++) {
                int col = n0 + wn * 64 + j * 8 + (lane & 3) * 2;
                float v0 = acc[t][j][half * 2 + 0] + bias[col];
                float v1 = acc[t][j][half * 2 + 1] + bias[col + 1];
                if (ACCUM) {
                    float2 o = *(const float2*)(crow + col);
                    v0 += o.x; v1 += o.y;
                }
                if (WF32) *(float2*)(crow + col) = make_float2(v0, v1);
                if (WHALF) {
                    __half h0 = __float2half_rn(fmaxf(v0, 0.0f));
                    __half h1 = __float2half_rn(fmaxf(v1, 0.0f));
                    *(__half2*)(Oh + (size_t)m * DH + col) = __half2{h0, h1};
                }
            }
        }
    }
}

// ---------------------------------------------------------------------------
// sigma = exp(relu(h) @ w_out + b_out), one warp per point
// ---------------------------------------------------------------------------
__global__ void sigma_kernel(const float* __restrict__ w_out,
                             const float* __restrict__ b_out,
                             float* __restrict__ out) {
    int gtid = blockIdx.x * blockDim.x + threadIdx.x;
    int n = gtid >> 5, lane = gtid & 31;
    if (n >= NPTS) return;
    const float* hrow = g_h + (size_t)n * DH;
    float s = 0.0f;
    #pragma unroll
    for (int k = lane; k < DH; k += 32)
        s = fmaf(fmaxf(hrow[k], 0.0f), w_out[k], s);
    #pragma unroll
    for (int off = 16; off > 0; off >>= 1)
        s += __shfl_down_sync(0xFFFFFFFF, s, off);
    if (lane == 0) out[n] = expf(s + b_out[0]);
}

// ---------------------------------------------------------------------------
// Launch
// ---------------------------------------------------------------------------
template <typename T>
static T* sym(const T& s) {
    void* p = nullptr;
    cudaGetSymbolAddress(&p, s);
    return (T*)p;
}

extern "C" void kernel_launch(void* const* d_in, const int* in_sizes, int n_in,
                              void* d_out, int out_size) {
    const float* world_xyz = (const float*)d_in[0];
    const float* c2w       = (const float*)d_in[1];
    const float* k_mat     = (const float*)d_in[2];
    const float* features  = (const float*)d_in[3];
    const float* lin_in_w  = (const float*)d_in[4];
    const float* lin_in_b  = (const float*)d_in[5];
    const float* lin_z_w   = (const float*)d_in[6];
    const float* lin_z_b   = (const float*)d_in[7];
    const float* fc0_w     = (const float*)d_in[8];
    const float* fc0_b     = (const float*)d_in[9];
    const float* fc1_w     = (const float*)d_in[10];
    const float* fc1_b     = (const float*)d_in[11];
    const float* lin_out_w = (const float*)d_in[12];
    const float* lin_out_b = (const float*)d_in[13];
    float* out = (float*)d_out;

    cudaFuncSetAttribute(gemm_tc_kernel<true,  true,  true >, cudaFuncAttributeMaxDynamicSharedMemorySize, SMEMSZ);
    cudaFuncSetAttribute(gemm_tc_kernel<false, false, true >, cudaFuncAttributeMaxDynamicSharedMemorySize, SMEMSZ);
    cudaFuncSetAttribute(gemm_tc_kernel<true,  true,  false>, cudaFuncAttributeMaxDynamicSharedMemorySize, SMEMSZ);

    float* p_enc = (float*)sym(g_enc);
    float* p_h   = (float*)sym(g_h);
    float* p_win = (float*)sym(g_win);
    __half* p_al = (__half*)sym(g_al);
    __half* p_t  = (__half*)sym(g_t);
    __half* p_u  = (__half*)sym(g_u);
    __half* p_wz = (__half*)sym(g_wz);
    __half* p_w0 = (__half*)sym(g_w0);
    __half* p_w1 = (__half*)sym(g_w1);

    pad_win_kernel<<<(DENC * DH + 255) / 256, 256>>>(lin_in_w);
    enc_kernel<<<(NPTS + 255) / 256, 256>>>(world_xyz, c2w, k_mat);
    bilinear_kernel<<<NPTS, 256>>>(features);

    int wtot = NBLK * DH * DH;
    conv_w_kernel<<<(wtot + 255) / 256, 256>>>(lin_z_w, p_wz, wtot);
    conv_w_kernel<<<(wtot + 255) / 256, 256>>>(fc0_w,   p_w0, wtot);
    conv_w_kernel<<<(wtot + 255) / 256, 256>>>(fc1_w,   p_w1, wtot);

    // h = enc @ win + b (fp32 FFMA, K=64)
    gemm_in_kernel<<<dim3(DH / 128, NPTS / 128), 256>>>(p_enc, p_win, lin_in_b,
                                                        p_h, NPTS, DH, DENC);

    dim3 grid(DH / TBN, NPTS / TBM);   // (4, 768)
    for (int i = 0; i < NBLK; i++) {
        size_t wo = (size_t)i * DH * DH;
        // h += aligned @ Wz + bz ;  t = relu(h) fp16
        gemm_tc_kernel<true, true, true><<<grid, 256, SMEMSZ>>>(
            p_al, p_wz + wo, lin_z_b + (size_t)i * DH, p_h, p_t);
        // net = relu(h) @ W0 + b0 ;  u = relu(net) fp16
        gemm_tc_kernel<false, false, true><<<grid, 256, SMEMSZ>>>(
            p_t, p_w0 + wo, fc0_b + (size_t)i * DH, nullptr, p_u);
        // h += relu(net) @ W1 + b1
        gemm_tc_kernel<true, true, false><<<grid, 256, SMEMSZ>>>(
            p_u, p_w1 + wo, fc1_b + (size_t)i * DH, p_h, nullptr);
    }

    sigma_kernel<<<(NPTS * 32 + 255) / 256, 256>>>(lin_out_w, lin_out_b, out);
}